// round 1
// baseline (speedup 1.0000x reference)
#include <cuda_runtime.h>
#include <cstdint>

// ---------------------------------------------------------------------------
// InflateHexToVertex:
//   out[b,n,v] = b[v] + sum_j mask(idx[n,j]) * ( hex[b, idx[n,j], :] @ W[j*D:(j+1)*D, v] )
//
// Factored as:
//   Z[j,t,b,v] = hex[b,t,:] @ W[j*D:(j+1)*D, :]      (small GEMM, 1.6 GFLOP)
//   out[b,n,v] = b[v] + sum_j (idx[n,j] >= 0) * Z[j, idx[n,j], b, v]
//
// Z is 25.2 MB -> lives in a __device__ scratch array, stays L2-resident.
// ---------------------------------------------------------------------------

#define GEMM_MT 128
#define GEMM_NT 64
#define GEMM_K  128
#define GEMM_THREADS 256

// scratch: Z[j][t][b][v]  (3, T<=512, B<=32, V=128) = 25.2 MB
__device__ float g_Z[3 * 512 * 32 * 128];
__device__ int g_is64;

// --- detect whether the index tensor is int64 or int32 ----------------------
// Values are in [-1, T). If stored as int64 (little-endian), every odd 32-bit
// word is the sign extension (0 or -1) of the preceding word. Check 64 pairs.
__global__ void detect_idx_dtype(const int* __restrict__ raw, int nwords) {
    if (threadIdx.x == 0 && blockIdx.x == 0) {
        int npairs = nwords / 2;
        if (npairs > 64) npairs = 64;
        int is64 = 1;
        for (int i = 0; i < npairs; ++i) {
            int lo = raw[2 * i];
            int hi = raw[2 * i + 1];
            if (hi != ((lo < 0) ? -1 : 0)) { is64 = 0; break; }
        }
        g_is64 = is64;
    }
}

// --- Z = hex(16384x128) @ W(384x128), written as Z[j][t][b][v] ---------------
// 128x64 tile, 8x4 microtile per thread, K=128 in one shot.
// SMEM: As[k][m] (transposed A, 64KB) + Bs[k][n] (32KB) = 96KB dynamic.
__global__ void gemm_z(const float* __restrict__ A, const float* __restrict__ W,
                       int M, int T, int B, int V) {
    extern __shared__ float sm[];
    float* As = sm;                      // [k][m]: k*128 + m
    float* Bs = sm + GEMM_K * GEMM_MT;   // [k][n]: k*64  + n

    const int tid = threadIdx.x;
    const int m0 = blockIdx.x * GEMM_MT;
    const int n0 = blockIdx.y * GEMM_NT;
    const int j  = n0 / V;               // which 128-col block of W (0..2)
    const int v0 = n0 - j * V;           // 0 or 64

    // Load A tile, transposing into As[k][m]. Mapping: lanes span m (so the
    // STS.32 per component is conflict-free); global reads are 16B/lane
    // strided (sector waste is negligible: A-tile traffic is tiny vs compute).
    #pragma unroll
    for (int it = 0; it < (GEMM_MT * GEMM_K / 4) / GEMM_THREADS; ++it) {  // 16
        int p  = it * GEMM_THREADS + tid;
        int m  = p & (GEMM_MT - 1);
        int k4 = p >> 7;                 // 0..31
        float4 av = make_float4(0.f, 0.f, 0.f, 0.f);
        if (m0 + m < M)
            av = *(const float4*)(A + (size_t)(m0 + m) * GEMM_K + k4 * 4);
        As[(k4 * 4 + 0) * GEMM_MT + m] = av.x;
        As[(k4 * 4 + 1) * GEMM_MT + m] = av.y;
        As[(k4 * 4 + 2) * GEMM_MT + m] = av.z;
        As[(k4 * 4 + 3) * GEMM_MT + m] = av.w;
    }
    // Load B tile: Bs[k][n] = W[j*128 + k][v0 + n]
    #pragma unroll
    for (int it = 0; it < (GEMM_K * GEMM_NT / 4) / GEMM_THREADS; ++it) {  // 8
        int p  = it * GEMM_THREADS + tid;
        int k  = p >> 4;
        int c4 = p & 15;
        *(float4*)(Bs + k * GEMM_NT + c4 * 4) =
            *(const float4*)(W + (size_t)(j * GEMM_K + k) * V + v0 + c4 * 4);
    }
    __syncthreads();

    const int tx = tid & 15;   // n: 4 cols
    const int ty = tid >> 4;   // m: 8 rows

    float acc[8][4];
    #pragma unroll
    for (int i = 0; i < 8; ++i)
        #pragma unroll
        for (int q = 0; q < 4; ++q) acc[i][q] = 0.f;

    #pragma unroll 8
    for (int k = 0; k < GEMM_K; ++k) {
        float4 a0 = *(const float4*)(As + k * GEMM_MT + ty * 8);
        float4 a1 = *(const float4*)(As + k * GEMM_MT + ty * 8 + 4);
        float4 bv = *(const float4*)(Bs + k * GEMM_NT + tx * 4);
        float a[8]  = {a0.x, a0.y, a0.z, a0.w, a1.x, a1.y, a1.z, a1.w};
        float bb[4] = {bv.x, bv.y, bv.z, bv.w};
        #pragma unroll
        for (int i = 0; i < 8; ++i)
            #pragma unroll
            for (int q = 0; q < 4; ++q)
                acc[i][q] += a[i] * bb[q];
    }

    // Write to Z[j][t][b][v0 + tx*4 ..]
    #pragma unroll
    for (int i = 0; i < 8; ++i) {
        int m = m0 + ty * 8 + i;
        if (m >= M) continue;
        int b = m / T;
        int t = m - b * T;
        float4 o = make_float4(acc[i][0], acc[i][1], acc[i][2], acc[i][3]);
        *(float4*)(g_Z + (((size_t)j * T + t) * B + b) * 128 + v0 + tx * 4) = o;
    }
}

// --- out[b,n,:] = bias + sum_j Z[j, idx[n,j], b, :] --------------------------
// One block per vertex n. A warp reads 512B contiguous from Z per (j,b):
// fully coalesced, L2-resident.
__global__ void gather_out(const int* __restrict__ idxw,
                           const float* __restrict__ bias,
                           float* __restrict__ out, int N, int T, int B) {
    const int n = blockIdx.x;
    const int s = 1 + g_is64;            // word stride per index element
    const int base = n * 3 * s;
    const int t0 = idxw[base];
    const int t1 = idxw[base + s];
    const int t2 = idxw[base + 2 * s];

    const float4* Z4 = (const float4*)g_Z;
    const float4* b4 = (const float4*)bias;

    const int total = B * 32;            // B * (V/4)
    for (int p = threadIdx.x; p < total; p += blockDim.x) {
        int b  = p >> 5;
        int v4 = p & 31;
        float4 acc = __ldg(b4 + v4);
        if (t0 >= 0) {
            float4 z = Z4[(((size_t)0 * T + t0) * B + b) * 32 + v4];
            acc.x += z.x; acc.y += z.y; acc.z += z.z; acc.w += z.w;
        }
        if (t1 >= 0) {
            float4 z = Z4[(((size_t)1 * T + t1) * B + b) * 32 + v4];
            acc.x += z.x; acc.y += z.y; acc.z += z.z; acc.w += z.w;
        }
        if (t2 >= 0) {
            float4 z = Z4[(((size_t)2 * T + t2) * B + b) * 32 + v4];
            acc.x += z.x; acc.y += z.y; acc.z += z.z; acc.w += z.w;
        }
        *(float4*)(out + ((size_t)b * N + n) * 128 + v4 * 4) = acc;
    }
}

extern "C" void kernel_launch(void* const* d_in, const int* in_sizes, int n_in,
                              void* d_out, int out_size) {
    const float* hex  = (const float*)d_in[0];   // (B, T, D) f32
    const int*   idxw = (const int*)d_in[1];     // (N, 3) int32 or int64
    const float* W    = (const float*)d_in[2];   // (3D, V) f32
    const float* bias = (const float*)d_in[3];   // (V,) f32
    float*       out  = (float*)d_out;           // (B, N, V) f32

    const int V      = in_sizes[3];              // 128
    const int threeD = in_sizes[2] / V;          // 384
    const int D      = threeD / 3;               // 128
    const int BT     = in_sizes[0] / D;          // B*T = 16384
    const int N      = in_sizes[1] / 3;          // 20000
    const int B      = out_size / (N * V);       // 32
    const int T      = BT / B;                   // 512

    cudaFuncSetAttribute(gemm_z, cudaFuncAttributeMaxDynamicSharedMemorySize,
                         (GEMM_K * GEMM_MT + GEMM_K * GEMM_NT) * (int)sizeof(float));

    detect_idx_dtype<<<1, 32>>>(idxw, in_sizes[1]);

    dim3 g1((BT + GEMM_MT - 1) / GEMM_MT, (3 * V) / GEMM_NT);
    gemm_z<<<g1, GEMM_THREADS,
             (GEMM_K * GEMM_MT + GEMM_K * GEMM_NT) * sizeof(float)>>>(
        hex, W, BT, T, B, V);

    gather_out<<<N, 256>>>(idxw, bias, out, N, T, B);
}